// round 1
// baseline (speedup 1.0000x reference)
#include <cuda_runtime.h>
#include <cstdint>

#define NUM_GRAPHS 2048
#define NPG 64
#define DIM 256
#define HN 32
#define HG 64

typedef unsigned long long u64;

// scratch for per-graph mean features [2048 x 256] (static __device__ allowed)
__device__ float g_mean[NUM_GRAPHS * DIM];

__device__ __forceinline__ u64 dup2(float v) {
    u64 r;
    unsigned int u = __float_as_uint(v);
    asm("mov.b64 %0, {%1, %1};" : "=l"(r) : "r"(u));
    return r;
}
__device__ __forceinline__ void ffma2(u64 &d, u64 a, u64 b) {
    asm("fma.rn.f32x2 %0, %1, %2, %0;" : "+l"(d) : "l"(a), "l"(b));
}

// ---------------------------------------------------------------------------
// Kernel 1: per 4-graph group — node_out GEMM (f32x2) + per-graph mean to scratch
// grid = 512 blocks (4 graphs each), 256 threads, dyn smem = 98304 B
// smem: Ws [256][32] (8192 f) | Xs [4 graphs][64 nodes][64 k] xor-swizzled (16384 f)
// ---------------------------------------------------------------------------
__global__ __launch_bounds__(256, 2) void k_main(
    const float* __restrict__ X, const float* __restrict__ Wn,
    float* __restrict__ node_out)
{
    extern __shared__ float smem[];
    float* Ws = smem;          // 8192 floats
    float* Xs = smem + 8192;   // 16384 floats

    const int t = threadIdx.x;
    const int gbase = blockIdx.x * 4;

    // stage W_node (256x32 fp32 = 32 KB) once
    {
        const float4* src = (const float4*)Wn;
        float4* dst = (float4*)Ws;
#pragma unroll
        for (int i = 0; i < 8; i++) dst[t + 256 * i] = src[t + 256 * i];
    }

    // compute-phase thread mapping: gi = graph-in-group, nq = node quad, c = col group
    const int gi = t >> 6;
    const int u  = t & 63;
    const int c  = u & 3;        // cols 8c..8c+7
    const int nq = u >> 2;       // nodes 4nq..4nq+3
    const int cb = nq << 2;      // xor swizzle key (shared by the 4 nodes of the quad)

    const float* xrow = Xs + (gi * 64 + nq * 4) * 64;

    u64 acc[4][4];
#pragma unroll
    for (int i = 0; i < 4; i++)
#pragma unroll
        for (int j = 0; j < 4; j++) acc[i][j] = 0ULL;

    const float4* Xg = (const float4*)X;
    const long rowbase = (long)gbase * 64 * 64;  // float4 index of group's first row

    for (int ch = 0; ch < 4; ch++) {
        __syncthreads();   // previous chunk's reads done (also covers Ws on ch==0)

        // stage chunk: 4 graphs x 64 nodes x 64 k  (4096 float4), xor-swizzled rows
#pragma unroll
        for (int i = 0; i < 16; i++) {
            int idx = t + 256 * i;
            int kq = idx & 15;       // float4 index within chunk row
            int r  = idx >> 4;       // 0..255 : gi*64 + node
            float4 v = Xg[rowbase + (long)r * 64 + ch * 16 + kq];
            int n = r & 63;
            ((float4*)Xs)[(r << 4) + (kq ^ (n >> 2))] = v;
        }
        __syncthreads();

        // per-graph feature sums for this chunk: thread owns (graph gi, feature u)
        {
            float s = 0.f;
            const float* gb = Xs + gi * 4096;
#pragma unroll
            for (int q = 0; q < 16; q++) {
                int col = u ^ (q << 2);
                const float* p = gb + q * 256 + col;
                s += p[0] + p[64] + p[128] + p[192];
            }
            g_mean[(gbase + gi) * DIM + ch * 64 + u] = s * (1.0f / 64.0f);
        }

        // main GEMM accumulate: 4 nodes x 8 cols per thread, packed f32x2 over col pairs
#pragma unroll 2
        for (int k = 0; k < 64; k++) {
            int col = k ^ cb;
            float xv0 = xrow[col];
            float xv1 = xrow[col + 64];
            float xv2 = xrow[col + 128];
            float xv3 = xrow[col + 192];
            u64 x0 = dup2(xv0), x1 = dup2(xv1), x2 = dup2(xv2), x3 = dup2(xv3);
            const ulonglong2* wkv =
                (const ulonglong2*)(Ws + (ch * 64 + k) * 32 + c * 8);
            ulonglong2 wa = wkv[0];
            ulonglong2 wb = wkv[1];
            ffma2(acc[0][0], x0, wa.x); ffma2(acc[0][1], x0, wa.y);
            ffma2(acc[0][2], x0, wb.x); ffma2(acc[0][3], x0, wb.y);
            ffma2(acc[1][0], x1, wa.x); ffma2(acc[1][1], x1, wa.y);
            ffma2(acc[1][2], x1, wb.x); ffma2(acc[1][3], x1, wb.y);
            ffma2(acc[2][0], x2, wa.x); ffma2(acc[2][1], x2, wa.y);
            ffma2(acc[2][2], x2, wb.x); ffma2(acc[2][3], x2, wb.y);
            ffma2(acc[3][0], x3, wa.x); ffma2(acc[3][1], x3, wa.y);
            ffma2(acc[3][2], x3, wb.x); ffma2(acc[3][3], x3, wb.y);
        }
    }

    // epilogue: write node_out (each acc u64 = 2 adjacent cols)
    {
        u64* outp = (u64*)node_out;
#pragma unroll
        for (int i = 0; i < 4; i++) {
            long node = (long)gbase * 64 + gi * 64 + nq * 4 + i;
            u64* p = outp + node * 16 + c * 4;
            p[0] = acc[i][0];
            p[1] = acc[i][1];
            p[2] = acc[i][2];
            p[3] = acc[i][3];
        }
    }
}

// ---------------------------------------------------------------------------
// Kernel 2: graph_out[g][j] = b[j] + mean[g][:] @ W_graph[:, j]
// grid = 256 blocks (8 graphs each), 256 threads, dyn smem = 67584 B
// ---------------------------------------------------------------------------
__global__ __launch_bounds__(256) void k_graph(
    const float* __restrict__ Wg, const float* __restrict__ bg,
    float* __restrict__ graph_out)
{
    extern __shared__ float smem2[];
    float* Wgs    = smem2;            // 16384 floats [d][64]
    float* mean_s = smem2 + 16384;    // 256
    float* red    = smem2 + 16640;    // 256

    const int t = threadIdx.x;
    {
        const float4* src = (const float4*)Wg;
        float4* dst = (float4*)Wgs;
#pragma unroll
        for (int i = 0; i < 16; i++) dst[t + 256 * i] = src[t + 256 * i];
    }
    const int j = t & 63;
    const int p = t >> 6;
    const float bj = bg[j];
    const int g0 = blockIdx.x * 8;

    for (int gg = 0; gg < 8; gg++) {
        int g = g0 + gg;
        __syncthreads();                       // Wgs ready / red reads done
        mean_s[t] = g_mean[g * DIM + t];
        __syncthreads();
        float s = 0.f;
        const float* mp = mean_s + p * 64;
        const float* wp = Wgs + p * 64 * 64 + j;
#pragma unroll 8
        for (int d = 0; d < 64; d++) s += mp[d] * wp[d * 64];
        red[t] = s;
        __syncthreads();
        if (p == 0)
            graph_out[g * 64 + j] = bj + red[j] + red[j + 64] + red[j + 128] + red[j + 192];
    }
}

// ---------------------------------------------------------------------------
extern "C" void kernel_launch(void* const* d_in, const int* in_sizes, int n_in,
                              void* d_out, int out_size) {
    const float* X  = (const float*)d_in[0];
    // d_in[1] = batch (int32) — layout is 64 consecutive nodes per graph, implicit
    const float* Wg = (const float*)d_in[2];
    const float* bg = (const float*)d_in[3];
    const float* Wn = (const float*)d_in[4];
    float* out = (float*)d_out;

    (void)in_sizes; (void)n_in; (void)out_size;

    cudaFuncSetAttribute(k_main,  cudaFuncAttributeMaxDynamicSharedMemorySize, 98304);
    cudaFuncSetAttribute(k_graph, cudaFuncAttributeMaxDynamicSharedMemorySize, 67584);

    // output layout: graph_out [2048*64] first, then node_out [131072*32]
    k_main<<<512, 256, 98304>>>(X, Wn, out + NUM_GRAPHS * HG);
    k_graph<<<256, 256, 67584>>>(Wg, bg, out);
}

// round 3
// speedup vs baseline: 1.0773x; 1.0773x over previous
#include <cuda_runtime.h>
#include <cstdint>

#define NUM_GRAPHS 2048
#define DIM 256
#define HN 32
#define HG 64

typedef unsigned long long u64;
typedef unsigned int u32;

// per-graph column SUMS (not divided by 64) [2048 x 256]
__device__ float g_sum[NUM_GRAPHS * DIM];

__device__ __forceinline__ u64 dup2(float v) {
    u64 r; u32 u = __float_as_uint(v);
    asm("mov.b64 %0, {%1, %1};" : "=l"(r) : "r"(u));
    return r;
}
__device__ __forceinline__ void ffma2(u64 &d, u64 a, u64 b) {
    asm("fma.rn.f32x2 %0, %1, %2, %0;" : "+l"(d) : "l"(a), "l"(b));
}

// ---------------------------------------------------------------------------
// k_main: CTA = 128 nodes (2 graphs), 128 threads, grid 1024.
// Per-thread tile: 4 nodes x 8 cols. X regs per 16-k chunk; w from smem
// (broadcast-friendly). f32x2 accumulators. Also emits per-graph column sums.
// smem: Ws[256][32] (32KB) | Xs[128][20] pad+xor-swiz势 (10240B) | scr (6144B)
// ---------------------------------------------------------------------------
#define PAD 20
#define SM_WS 0
#define SM_XS 8192            // float index
#define SM_SCR 10752          // float index (Xs = 2560 floats)
#define SMEM_FLOATS (10752 + 1536)

__global__ __launch_bounds__(128, 4) void k_main(
    const float* __restrict__ X, const float* __restrict__ Wn,
    float* __restrict__ node_out)
{
    extern __shared__ float sm[];
    float* Ws = sm + SM_WS;    // [k 256][c 32]
    float* Xs = sm + SM_XS;    // [row 128][PAD], quad-xor swizzled
    float4* scr = (float4*)(sm + SM_SCR);  // [thread 128][stride 3] float4

    const int t = threadIdx.x;

    // stage W_node (256x32 f32 = 2048 float4) once
    {
        const float4* src = (const float4*)Wn;
        float4* dst = (float4*)Ws;
#pragma unroll
        for (int i = 0; i < 16; i++) dst[t + 128 * i] = src[t + 128 * i];
    }

    const int rq = t >> 2;        // staging row base 0..31
    const int q  = t & 3;         // staging quad / compute col-group
    const int quad = t >> 2;      // compute node-quad 0..31 (nodes 4*quad..+3)
    const int cg = t & 3;         // compute cols 8*cg..8*cg+7
    const int sw = (quad >> 1) & 3;  // x-read xor key (same for the 4 nodes)

    const long tileRow = (long)blockIdx.x * 128;
    const float4* X4 = (const float4*)X;

    u64 acc[4][4];
#pragma unroll
    for (int i = 0; i < 4; i++)
#pragma unroll
        for (int j = 0; j < 4; j++) acc[i][j] = 0ULL;

    // prologue prefetch chunk 0
    float4 nv[4];
#pragma unroll
    for (int i = 0; i < 4; i++)
        nv[i] = X4[(tileRow + rq + 32 * i) * 64 + q];

#pragma unroll 1
    for (int ch = 0; ch < 16; ch++) {
        __syncthreads();   // previous chunk's smem reads done (covers Ws on ch0)

        // store staged rows (xor quad swizzle on pad-20 rows)
#pragma unroll
        for (int i = 0; i < 4; i++) {
            int r = rq + 32 * i;
            int pq = q ^ ((r >> 3) & 3);
            *(float4*)&Xs[r * PAD + pq * 4] = nv[i];
        }
        // per-graph partials: rows rq,rq+32 -> graph0 ; rq+64,rq+96 -> graph1
        {
            float4 p0 = make_float4(nv[0].x + nv[1].x, nv[0].y + nv[1].y,
                                    nv[0].z + nv[1].z, nv[0].w + nv[1].w);
            float4 p1 = make_float4(nv[2].x + nv[3].x, nv[2].y + nv[3].y,
                                    nv[2].z + nv[3].z, nv[2].w + nv[3].w);
            scr[t * 3 + 0] = p0;
            scr[t * 3 + 1] = p1;
        }
        __syncthreads();

        // prefetch next chunk (overlaps compute)
        if (ch < 15) {
#pragma unroll
            for (int i = 0; i < 4; i++)
                nv[i] = X4[(tileRow + rq + 32 * i) * 64 + (ch + 1) * 4 + q];
        }

        // g_sum reduction: 8 jobs on lanes spread across warps (t % 16 == 0)
        if ((t & 15) == 0) {
            int j = t >> 4;            // 0..7
            int g = j >> 2, qq = j & 3;
            float4 a = make_float4(0.f, 0.f, 0.f, 0.f);
#pragma unroll
            for (int rr = 0; rr < 32; rr++) {
                float4 b = scr[(rr * 4 + qq) * 3 + g];
                a.x += b.x; a.y += b.y; a.z += b.z; a.w += b.w;
            }
            *(float4*)&g_sum[(blockIdx.x * 2 + g) * DIM + ch * 16 + qq * 4] = a;
        }

        // compute: 16 k's in 4 groups of 4; x regs refreshed per group
        const float* wbase = Ws + (ch * 16) * 32 + cg * 8;
#pragma unroll
        for (int j = 0; j < 4; j++) {
            float xa[4][4];
#pragma unroll
            for (int i = 0; i < 4; i++) {
                int n = 4 * quad + i;
                *(float4*)xa[i] = *(const float4*)&Xs[n * PAD + ((j ^ sw) << 2)];
            }
#pragma unroll
            for (int kk = 0; kk < 4; kk++) {
                const int k = j * 4 + kk;
                u64 x0 = dup2(xa[0][kk]);
                u64 x1 = dup2(xa[1][kk]);
                u64 x2 = dup2(xa[2][kk]);
                u64 x3 = dup2(xa[3][kk]);
                const ulonglong2* wp = (const ulonglong2*)(wbase + k * 32);
                ulonglong2 wa = wp[0];
                ulonglong2 wb = wp[1];
                ffma2(acc[0][0], x0, wa.x); ffma2(acc[0][1], x0, wa.y);
                ffma2(acc[0][2], x0, wb.x); ffma2(acc[0][3], x0, wb.y);
                ffma2(acc[1][0], x1, wa.x); ffma2(acc[1][1], x1, wa.y);
                ffma2(acc[1][2], x1, wb.x); ffma2(acc[1][3], x1, wb.y);
                ffma2(acc[2][0], x2, wa.x); ffma2(acc[2][1], x2, wa.y);
                ffma2(acc[2][2], x2, wb.x); ffma2(acc[2][3], x2, wb.y);
                ffma2(acc[3][0], x3, wa.x); ffma2(acc[3][1], x3, wa.y);
                ffma2(acc[3][2], x3, wb.x); ffma2(acc[3][3], x3, wb.y);
            }
        }
    }

    // epilogue: node_out[node][cg*8 .. cg*8+7]
#pragma unroll
    for (int i = 0; i < 4; i++) {
        long node = tileRow + 4 * quad + i;
        u64* p = (u64*)(node_out + node * HN + cg * 8);
        ulonglong2 s0; s0.x = acc[i][0]; s0.y = acc[i][1];
        ulonglong2 s1; s1.x = acc[i][2]; s1.y = acc[i][3];
        *(ulonglong2*)(p + 0) = s0;
        *(ulonglong2*)(p + 2) = s1;
    }
}

// ---------------------------------------------------------------------------
// k_graph: graph_out[g][j] = b[j] + (g_sum[g][:]/64) @ W_graph[:, j]
// grid = 128 blocks (16 graphs each), 256 threads, smem = 81920 B
// thread (g = t&15, jq = t>>4) -> 4 outputs; W staged once, means transposed
// ---------------------------------------------------------------------------
__global__ __launch_bounds__(256) void k_graph(
    const float* __restrict__ Wg, const float* __restrict__ bg,
    float* __restrict__ graph_out)
{
    extern __shared__ float sm2[];
    float* Wgs = sm2;           // [256 d][64 j]  (16384 f)
    float* Ms  = sm2 + 16384;   // means transposed [256 d][16 g] (4096 f)

    const int t = threadIdx.x;
    const int gbase = blockIdx.x * 16;

    {
        const float4* W4 = (const float4*)Wg;
        float4* Wd = (float4*)Wgs;
#pragma unroll
        for (int i = 0; i < 16; i++) Wd[t + 256 * i] = W4[t + 256 * i];
    }
    {
        const float inv = 1.0f / 64.0f;
#pragma unroll
        for (int i = 0; i < 4; i++) {
            int idx = t + 256 * i;        // 0..1023
            int g = idx >> 6;             // 0..15
            int c4 = idx & 63;            // float4 within row
            float4 s = ((const float4*)(g_sum + (long)(gbase + g) * DIM))[c4];
            Ms[(c4 * 4 + 0) * 16 + g] = s.x * inv;
            Ms[(c4 * 4 + 1) * 16 + g] = s.y * inv;
            Ms[(c4 * 4 + 2) * 16 + g] = s.z * inv;
            Ms[(c4 * 4 + 3) * 16 + g] = s.w * inv;
        }
    }
    __syncthreads();

    const int g  = t & 15;
    const int jq = t >> 4;     // 0..15 -> cols 4jq..4jq+3
    float4 b4 = ((const float4*)bg)[jq];

    u64 acc01 = 0ULL, acc23 = 0ULL;
#pragma unroll 8
    for (int d = 0; d < 256; d++) {
        float m = Ms[d * 16 + g];
        u64 md = dup2(m);
        ulonglong2 w = *(const ulonglong2*)(Wgs + d * 64 + jq * 4);
        ffma2(acc01, md, w.x);
        ffma2(acc23, md, w.y);
    }
    float a0, a1, a2, a3;
    asm("mov.b64 {%0, %1}, %2;" : "=f"(a0), "=f"(a1) : "l"(acc01));
    asm("mov.b64 {%0, %1}, %2;" : "=f"(a2), "=f"(a3) : "l"(acc23));
    float4 r = make_float4(a0 + b4.x, a1 + b4.y, a2 + b4.z, a3 + b4.w);
    ((float4*)graph_out)[(long)(gbase + g) * 16 + jq] = r;
}

// ---------------------------------------------------------------------------
extern "C" void kernel_launch(void* const* d_in, const int* in_sizes, int n_in,
                              void* d_out, int out_size) {
    const float* X  = (const float*)d_in[0];
    // d_in[1] = batch (int32): 64 consecutive nodes per graph, implicit
    const float* Wg = (const float*)d_in[2];
    const float* bg = (const float*)d_in[3];
    const float* Wn = (const float*)d_in[4];
    float* out = (float*)d_out;
    (void)in_sizes; (void)n_in; (void)out_size;

    cudaFuncSetAttribute(k_main,  cudaFuncAttributeMaxDynamicSharedMemorySize,
                         SMEM_FLOATS * 4);
    cudaFuncSetAttribute(k_graph, cudaFuncAttributeMaxDynamicSharedMemorySize, 81920);

    // output layout: graph_out [2048*64] first, then node_out [131072*32]
    k_main<<<1024, 128, SMEM_FLOATS * 4>>>(X, Wn, out + NUM_GRAPHS * HG);
    k_graph<<<128, 256, 81920>>>(Wg, bg, out);
}

// round 4
// speedup vs baseline: 1.5333x; 1.4233x over previous
#include <cuda_runtime.h>
#include <cuda_bf16.h>
#include <cstdint>

#define NUM_GRAPHS 2048
#define DIM 256
#define HN 32
#define HG 64

typedef unsigned long long u64;
typedef unsigned int u32;

// ---- smem layout (bytes) ----
#define SM_XH 0u          // X hi  [128 r][64 k] bf16, SW128   (16384)
#define SM_XL 16384u      // X lo                               (16384)
#define SM_WH 32768u      // W^T hi [32 n][264 k] bf16 pad8     (16896)
#define SM_WL 49664u      // W^T lo                             (16896)
#define SM_SCR 66560u     // scratch 128 x float4               (4096)
#define SM_GS 70656u      // graph sums 2 x 256 f32             (2048)
#define SMEM_BYTES 72704
#define WROW 528          // bytes per W^T row (264 bf16)

__device__ __forceinline__ u32 smem_u32(const void* p) {
    u32 a;
    asm("{ .reg .u64 t; cvta.to.shared.u64 t, %1; cvt.u32.u64 %0, t; }" : "=r"(a) : "l"(p));
    return a;
}
__device__ __forceinline__ void ldsm4(u32& r0, u32& r1, u32& r2, u32& r3, u32 a) {
    asm volatile("ldmatrix.sync.aligned.m8n8.x4.shared.b16 {%0,%1,%2,%3}, [%4];"
        : "=r"(r0), "=r"(r1), "=r"(r2), "=r"(r3) : "r"(a));
}
__device__ __forceinline__ void mma16816(float* d, u32 a0, u32 a1, u32 a2, u32 a3,
                                         u32 b0, u32 b1) {
    asm volatile("mma.sync.aligned.m16n8k16.row.col.f32.bf16.bf16.f32 "
        "{%0,%1,%2,%3}, {%4,%5,%6,%7}, {%8,%9}, {%0,%1,%2,%3};"
        : "+f"(d[0]), "+f"(d[1]), "+f"(d[2]), "+f"(d[3])
        : "r"(a0), "r"(a1), "r"(a2), "r"(a3), "r"(b0), "r"(b1));
}
__device__ __forceinline__ u32 bits2(__nv_bfloat162 v) {
    u32 r; __builtin_memcpy(&r, &v, 4); return r;
}
__device__ __forceinline__ void split2(float x0, float x1, u32& hp, u32& lp) {
    __nv_bfloat162 h = __float22bfloat162_rn(make_float2(x0, x1));
    float2 f = __bfloat1622float2(h);
    __nv_bfloat162 l = __float22bfloat162_rn(make_float2(x0 - f.x, x1 - f.y));
    hp = bits2(h); lp = bits2(l);
}

// ---------------------------------------------------------------------------
// Fused kernel: CTA = 128 nodes = 2 graphs. grid 1024, 128 threads.
//   node_out = X @ Wn   (bf16 hi/lo 3-term mma.sync, fp32 accum)
//   graph_out = mean(X per graph) @ Wg + b   (fp32, epilogue)
// ---------------------------------------------------------------------------
__global__ __launch_bounds__(128, 3) void k_fused(
    const float* __restrict__ X, const float* __restrict__ Wn,
    const float* __restrict__ Wg, const float* __restrict__ bg,
    float* __restrict__ graph_out, float* __restrict__ node_out)
{
    extern __shared__ char smem[];
    const u32 sbase = smem_u32(smem);
    float4* scr = (float4*)(smem + SM_SCR);
    float*  gsum = (float*)(smem + SM_GS);

    const int t = threadIdx.x;
    const int w = t >> 5;
    const int lane = t & 31;
    const long tileRow = (long)blockIdx.x * 128;

    // ---- stage W^T hi/lo : Wn[256][32] f32 -> [n][264k] bf16 (pad rows) ----
    {
        const float4* W4 = (const float4*)Wn;
#pragma unroll
        for (int i = 0; i < 16; i++) {
            int idx = t + 128 * i;       // 2048 float4
            float4 v = W4[idx];
            int d = idx >> 3;            // k dim 0..255
            int n0 = (idx & 7) * 4;
            float vv[4] = {v.x, v.y, v.z, v.w};
#pragma unroll
            for (int j = 0; j < 4; j++) {
                __nv_bfloat16 h = __float2bfloat16_rn(vv[j]);
                float rsd = vv[j] - __bfloat162float(h);
                __nv_bfloat16 l = __float2bfloat16_rn(rsd);
                u32 off = (u32)(n0 + j) * WROW + (u32)d * 2;
                *(__nv_bfloat16*)(smem + SM_WH + off) = h;
                *(__nv_bfloat16*)(smem + SM_WL + off) = l;
            }
        }
        // zero graph-sum accumulator
        *(float4*)&gsum[t * 4] = make_float4(0.f, 0.f, 0.f, 0.f);
    }

    // fragment address precompute
    const int aq = lane >> 3;           // ldmatrix address group
    const int ai = lane & 7;
    const u32 amask = (u32)ai << 4;     // SW128 xor key (row&7 == ai)
    const u32 akb = (u32)(aq >> 1) * 16;
    const u32 arow0 = (u32)(w * 32 + ((aq & 1) ? 8 : 0) + ai) * 128;  // mt=0
    const u32 bbase = (u32)(aq * 8 + ai) * WROW;

    float acc[2][4][4];
#pragma unroll
    for (int mt = 0; mt < 2; mt++)
#pragma unroll
        for (int nt = 0; nt < 4; nt++)
#pragma unroll
            for (int e = 0; e < 4; e++) acc[mt][nt][e] = 0.f;

    const float4* X4 = (const float4*)X;

#pragma unroll 1
    for (int ch = 0; ch < 4; ch++) {
        __syncthreads();   // prior chunk's smem reads done (covers W staging on ch0)

        // ---- stage X chunk [128 r][64 k]: hi/lo bf16, SW128 swizzle ----
        float4 p0 = make_float4(0.f, 0.f, 0.f, 0.f);
        float4 p1 = make_float4(0.f, 0.f, 0.f, 0.f);
#pragma unroll
        for (int i = 0; i < 16; i++) {
            int idx = t + 128 * i;
            int r = idx >> 4;            // row 0..127
            int c4 = idx & 15;           // float4 within row
            float4 v = X4[(tileRow + r) * 64 + ch * 16 + c4];
            uint2 hp, lp;
            split2(v.x, v.y, hp.x, lp.x);
            split2(v.z, v.w, hp.y, lp.y);
            u32 off = (u32)r * 128u + (((u32)c4 * 8u) ^ (((u32)r & 7u) << 4));
            *(uint2*)(smem + SM_XH + off) = hp;
            *(uint2*)(smem + SM_XL + off) = lp;
            if (i < 8) { p0.x += v.x; p0.y += v.y; p0.z += v.z; p0.w += v.w; }
            else       { p1.x += v.x; p1.y += v.y; p1.z += v.z; p1.w += v.w; }
        }
        scr[t * 2 + 0] = p0;
        scr[t * 2 + 1] = p1;
        __syncthreads();

        // ---- graph column-sum reduce (warp 0 lanes) ----
        if (t < 32) {
            int c4 = t & 15, g = t >> 4;
            float4 a = scr[c4 * 2 + g];
#pragma unroll
            for (int rb = 1; rb < 8; rb++) {
                float4 b = scr[(c4 + 16 * rb) * 2 + g];
                a.x += b.x; a.y += b.y; a.z += b.z; a.w += b.w;
            }
            float4* gp = (float4*)&gsum[g * 256 + ch * 64 + c4 * 4];
            float4 cur = gp[0];
            cur.x += a.x; cur.y += a.y; cur.z += a.z; cur.w += a.w;
            gp[0] = cur;
        }

        // ---- compute: 4 k16-steps ----
#pragma unroll
        for (int ks = 0; ks < 4; ks++) {
            const u32 koff = ((u32)ks * 32 + akb) ^ amask;
            u32 ah[2][4], al[2][4];
            ldsm4(ah[0][0], ah[0][1], ah[0][2], ah[0][3], sbase + SM_XH + arow0 + koff);
            ldsm4(ah[1][0], ah[1][1], ah[1][2], ah[1][3], sbase + SM_XH + arow0 + 2048 + koff);
            ldsm4(al[0][0], al[0][1], al[0][2], al[0][3], sbase + SM_XL + arow0 + koff);
            ldsm4(al[1][0], al[1][1], al[1][2], al[1][3], sbase + SM_XL + arow0 + 2048 + koff);

            const u32 bko = (u32)(ch * 64 + ks * 16) * 2;
            u32 bh0[4], bh1[4], bl0[4], bl1[4];
            ldsm4(bh0[0], bh0[1], bh0[2], bh0[3], sbase + SM_WH + bbase + bko);
            ldsm4(bh1[0], bh1[1], bh1[2], bh1[3], sbase + SM_WH + bbase + bko + 16);
            ldsm4(bl0[0], bl0[1], bl0[2], bl0[3], sbase + SM_WL + bbase + bko);
            ldsm4(bl1[0], bl1[1], bl1[2], bl1[3], sbase + SM_WL + bbase + bko + 16);

#pragma unroll
            for (int mt = 0; mt < 2; mt++)
#pragma unroll
                for (int nt = 0; nt < 4; nt++) {
                    mma16816(acc[mt][nt], ah[mt][0], ah[mt][1], ah[mt][2], ah[mt][3],
                             bh0[nt], bh1[nt]);
                    mma16816(acc[mt][nt], ah[mt][0], ah[mt][1], ah[mt][2], ah[mt][3],
                             bl0[nt], bl1[nt]);
                    mma16816(acc[mt][nt], al[mt][0], al[mt][1], al[mt][2], al[mt][3],
                             bh0[nt], bh1[nt]);
                }
        }
    }

    // ---- node_out epilogue ----
    {
        const int rr = lane >> 2;
        const int cc = (lane & 3) * 2;
#pragma unroll
        for (int mt = 0; mt < 2; mt++) {
            long r0 = tileRow + w * 32 + mt * 16 + rr;
#pragma unroll
            for (int nt = 0; nt < 4; nt++) {
                float* dd = acc[mt][nt];
                int c0 = nt * 8 + cc;
                *(float2*)(node_out + r0 * HN + c0) = make_float2(dd[0], dd[1]);
                *(float2*)(node_out + (r0 + 8) * HN + c0) = make_float2(dd[2], dd[3]);
            }
        }
    }

    // ---- graph head epilogue: out[g][:] = (gsum[g]/64) @ Wg + b ----
    __syncthreads();
    {
        const int g = t >> 6;
        const int p = (t >> 4) & 3;
        const int jq = t & 15;
        const float4* Wg4 = (const float4*)Wg;
        const float inv = 1.0f / 64.0f;
        float4 a = make_float4(0.f, 0.f, 0.f, 0.f);
        const float* gs = gsum + g * 256;
#pragma unroll 8
        for (int d = p * 64; d < p * 64 + 64; d++) {
            float m = gs[d] * inv;
            float4 wv = __ldg(&Wg4[d * 16 + jq]);
            a.x += m * wv.x; a.y += m * wv.y; a.z += m * wv.z; a.w += m * wv.w;
        }
        scr[t] = a;
    }
    __syncthreads();
    if (t < 32) {
        int g = t >> 4, jq = t & 15;
        float4 a = scr[g * 64 + jq];
#pragma unroll
        for (int p = 1; p < 4; p++) {
            float4 b = scr[g * 64 + p * 16 + jq];
            a.x += b.x; a.y += b.y; a.z += b.z; a.w += b.w;
        }
        float4 b4 = __ldg(&((const float4*)bg)[jq]);
        a.x += b4.x; a.y += b4.y; a.z += b4.z; a.w += b4.w;
        ((float4*)graph_out)[(blockIdx.x * 2 + g) * 16 + jq] = a;
    }
}

// ---------------------------------------------------------------------------
extern "C" void kernel_launch(void* const* d_in, const int* in_sizes, int n_in,
                              void* d_out, int out_size) {
    const float* X  = (const float*)d_in[0];
    // d_in[1] = batch (int32): 64 consecutive nodes per graph, implicit
    const float* Wg = (const float*)d_in[2];
    const float* bg = (const float*)d_in[3];
    const float* Wn = (const float*)d_in[4];
    float* out = (float*)d_out;
    (void)in_sizes; (void)n_in; (void)out_size;

    cudaFuncSetAttribute(k_fused, cudaFuncAttributeMaxDynamicSharedMemorySize, SMEM_BYTES);

    // output layout: graph_out [2048*64] first, then node_out [131072*32]
    k_fused<<<1024, 128, SMEM_BYTES>>>(X, Wn, Wg, bg, out, out + NUM_GRAPHS * HG);
}